// round 5
// baseline (speedup 1.0000x reference)
#include <cuda_runtime.h>
#include <cstdint>

#define BATCH 128
#define DG 512
#define DH 1024
#define LAM 0.95f
#define ETA 0.5f
#define LN_EPS 1e-5f

// Fused-kernel geometry: 3 gangs x 128 blocks; block owns 8 rows.
#define F_ROWS 8
#define F_GANG_BLOCKS 128
#define F_GANGS 3
#define F_GRID (F_GANGS * F_GANG_BLOCKS)
#define F_TILE (F_ROWS * DH)
// smem: 2 tile buffers + s_h + s_red
#define F_SMEM ((2 * F_TILE + DH + 32) * sizeof(float))

// Scratch (allocation-free)
__device__ float g_base[BATCH * DH];
__device__ float g_y0[BATCH * DH];
__device__ float g_y1[BATCH * DH];
__device__ int   g_arrive[F_GANGS];

// ---------------------------------------------------------------------------
__device__ __forceinline__ void cp_async16(void* sdst, const void* gsrc) {
    uint32_t s = (uint32_t)__cvta_generic_to_shared(sdst);
    asm volatile("cp.async.cg.shared.global [%0], [%1], 16;" :: "r"(s), "l"(gsrc));
}
#define CP_COMMIT() asm volatile("cp.async.commit_group;")
#define CP_WAIT0()  asm volatile("cp.async.wait_group 0;")

// ---------------------------------------------------------------------------
// Kernel 1: base = h_prev@Wh^T + z@Wg^T + bh. Also zeroes gang counters.
// ---------------------------------------------------------------------------
__global__ void base_gemm_kernel(const float* __restrict__ Hp,
                                 const float* __restrict__ Z,
                                 const float* __restrict__ Wh,
                                 const float* __restrict__ Wg,
                                 const float* __restrict__ bh)
{
    __shared__ float Hs[32][33];
    __shared__ float Ws[32][33];

    const int tid = threadIdx.x;
    if (blockIdx.x == 0 && blockIdx.y == 0 && tid < F_GANGS)
        g_arrive[tid] = 0;

    const int tx = tid & 15;
    const int ty = tid >> 4;
    const int bm0 = blockIdx.x * 32;
    const int n0  = blockIdx.y * 32;

    float acc00 = 0.f, acc01 = 0.f, acc10 = 0.f, acc11 = 0.f;

    for (int k0 = 0; k0 < DH + DG; k0 += 32) {
        const float* src;
        const float* wsrc;
        int K, kk0;
        if (k0 < DH) { src = Hp; wsrc = Wh; K = DH; kk0 = k0; }
        else         { src = Z;  wsrc = Wg; K = DG; kk0 = k0 - DH; }

        #pragma unroll
        for (int l = 0; l < 4; l++) {
            int idx = tid + l * 256;
            int r = idx >> 5, c = idx & 31;
            Hs[r][c] = src[(bm0 + r) * K + kk0 + c];
            Ws[r][c] = wsrc[(n0 + r) * K + kk0 + c];
        }
        __syncthreads();

        #pragma unroll
        for (int kk = 0; kk < 32; kk++) {
            float h0 = Hs[ty * 2][kk];
            float h1 = Hs[ty * 2 + 1][kk];
            float w0 = Ws[tx * 2][kk];
            float w1 = Ws[tx * 2 + 1][kk];
            acc00 += h0 * w0; acc01 += h0 * w1;
            acc10 += h1 * w0; acc11 += h1 * w1;
        }
        __syncthreads();
    }

    const int r0 = bm0 + ty * 2;
    const int c0 = n0 + tx * 2;
    const float bias0 = bh[c0];
    const float bias1 = bh[c0 + 1];
    g_base[r0 * DH + c0]           = acc00 + bias0;
    g_base[r0 * DH + c0 + 1]       = acc01 + bias1;
    g_base[(r0 + 1) * DH + c0]     = acc10 + bias0;
    g_base[(r0 + 1) * DH + c0 + 1] = acc11 + bias1;
}

// ---------------------------------------------------------------------------
// In-block LN+ReLU: 256 threads, h[b] (1024 floats) into s_h. Trailing sync.
// ---------------------------------------------------------------------------
__device__ __forceinline__ void compute_h(const float* __restrict__ base_b,
                                          const float* __restrict__ y_b,
                                          const float* __restrict__ gamma,
                                          const float* __restrict__ beta,
                                          float* __restrict__ s_h,
                                          float* __restrict__ s_red,
                                          int t)
{
    const int w = t >> 5, lane = t & 31;

    float4 x = reinterpret_cast<const float4*>(base_b)[t];
    if (y_b) {
        float4 y = reinterpret_cast<const float4*>(y_b)[t];
        x.x += y.x; x.y += y.y; x.z += y.z; x.w += y.w;
    }
    float s  = (x.x + x.y) + (x.z + x.w);
    float ss = fmaf(x.x, x.x, x.y * x.y) + fmaf(x.z, x.z, x.w * x.w);

    #pragma unroll
    for (int o = 16; o > 0; o >>= 1) {
        s  += __shfl_xor_sync(0xffffffffu, s,  o);
        ss += __shfl_xor_sync(0xffffffffu, ss, o);
    }
    if (lane == 0) { s_red[w] = s; s_red[8 + w] = ss; }
    __syncthreads();
    if (t < 32) {
        float a = (lane < 8) ? s_red[lane]     : 0.f;
        float c = (lane < 8) ? s_red[8 + lane] : 0.f;
        #pragma unroll
        for (int o = 4; o > 0; o >>= 1) {
            a += __shfl_xor_sync(0xffffffffu, a, o);
            c += __shfl_xor_sync(0xffffffffu, c, o);
        }
        if (lane == 0) { s_red[0] = a; s_red[1] = c; }
    }
    __syncthreads();

    const float mu   = s_red[0] * (1.0f / DH);
    const float var  = s_red[1] * (1.0f / DH) - mu * mu;
    const float rstd = rsqrtf(var + LN_EPS);

    float4 g  = reinterpret_cast<const float4*>(gamma)[t];
    float4 be = reinterpret_cast<const float4*>(beta)[t];
    float4 h;
    h.x = fmaxf(0.f, (x.x - mu) * rstd * g.x + be.x);
    h.y = fmaxf(0.f, (x.y - mu) * rstd * g.y + be.y);
    h.z = fmaxf(0.f, (x.z - mu) * rstd * g.z + be.z);
    h.w = fmaxf(0.f, (x.w - mu) * rstd * g.w + be.w);
    reinterpret_cast<float4*>(s_h)[t] = h;
    __syncthreads();
}

// ---------------------------------------------------------------------------
// Kernel 2 (x2): h = relu(LN(base [+ yin])), then yout = A@h.
// grid = (16 chunks, 128 batches), 256 thr.
// ---------------------------------------------------------------------------
__global__ __launch_bounds__(256)
void matvec_ln_kernel(const float* __restrict__ A,
                      const float* __restrict__ yin,    // may be null
                      float* __restrict__ yout,
                      const float* __restrict__ gamma,
                      const float* __restrict__ beta)
{
    __shared__ float s_h[DH];
    __shared__ float s_red[16];

    const int b = blockIdx.y;
    const int chunk = blockIdx.x;
    const int t = threadIdx.x;
    const int w = t >> 5, lane = t & 31;

    compute_h(g_base + b * DH, yin ? yin + b * DH : nullptr,
              gamma, beta, s_h, s_red, t);

    const float4* __restrict__ Ab =
        reinterpret_cast<const float4*>(A + (size_t)b * DH * DH);
    const float4* h4 = reinterpret_cast<const float4*>(s_h);

    #pragma unroll
    for (int rr = 0; rr < 8; rr += 2) {
        const int r0 = chunk * 64 + w * 8 + rr;
        const float4* Ar0 = Ab + (size_t)r0 * 256;
        const float4* Ar1 = Ar0 + 256;

        float a00 = 0.f, a01 = 0.f, a10 = 0.f, a11 = 0.f;
        #pragma unroll
        for (int it = 0; it < 8; it += 2) {
            float4 v00 = __ldcs(Ar0 + lane + (it + 0) * 32);
            float4 v01 = __ldcs(Ar0 + lane + (it + 1) * 32);
            float4 v10 = __ldcs(Ar1 + lane + (it + 0) * 32);
            float4 v11 = __ldcs(Ar1 + lane + (it + 1) * 32);
            float4 h0  = h4[lane + (it + 0) * 32];
            float4 h1  = h4[lane + (it + 1) * 32];
            a00 += v00.x * h0.x + v00.y * h0.y + v00.z * h0.z + v00.w * h0.w;
            a01 += v01.x * h1.x + v01.y * h1.y + v01.z * h1.z + v01.w * h1.w;
            a10 += v10.x * h0.x + v10.y * h0.y + v10.z * h0.z + v10.w * h0.w;
            a11 += v11.x * h1.x + v11.y * h1.y + v11.z * h1.z + v11.w * h1.w;
        }
        float acc0 = a00 + a01;
        float acc1 = a10 + a11;
        #pragma unroll
        for (int o = 16; o > 0; o >>= 1) {
            acc0 += __shfl_xor_sync(0xffffffffu, acc0, o);
            acc1 += __shfl_xor_sync(0xffffffffu, acc1, o);
        }
        if (lane == 0) {
            yout[b * DH + r0]     = acc0;
            yout[b * DH + r0 + 1] = acc1;
        }
    }
}

// ---------------------------------------------------------------------------
// Kernel 3: fused (3rd matvec + update), persistent gangs with cp.async
// double-buffered prefetch. Gang = 128 blocks; block owns 8 rows.
// 384 blocks, 69.8KB smem -> 3 blocks/SM -> all co-resident (444 slots).
// ---------------------------------------------------------------------------
__global__ __launch_bounds__(256)
void fused_mv3_update_kernel(const float* __restrict__ A,
                             const float* __restrict__ yin,   // y1
                             const float* __restrict__ gamma,
                             const float* __restrict__ beta,
                             float* __restrict__ outH,
                             float* __restrict__ outA)
{
    extern __shared__ float sm[];
    float* tiles = sm;                  // [2][F_TILE]
    float* s_h   = sm + 2 * F_TILE;     // 1024
    float* s_red = s_h + DH;            // 32

    const int gang = blockIdx.x / F_GANG_BLOCKS;
    const int cb   = blockIdx.x % F_GANG_BLOCKS;   // row-chunk within gang
    const int t    = threadIdx.x;
    const int w    = t >> 5, lane = t & 31;

    // prefetch first tile into buffer 0
    {
        const float* Ab = A + (size_t)gang * DH * DH + (size_t)(cb * F_ROWS) * DH;
        #pragma unroll
        for (int k = 0; k < F_ROWS; k++)
            cp_async16(tiles + k * DH + t * 4, Ab + k * DH + t * 4);
        CP_COMMIT();
    }

    int iter = 0;
    for (int b = gang; b < BATCH; b += F_GANGS, iter++) {
        const int cur = iter & 1;
        float* tile = tiles + cur * F_TILE;
        const float4* tile4 = reinterpret_cast<const float4*>(tile);
        const float4* h4 = reinterpret_cast<const float4*>(s_h);

        // ---- h2 = relu(LN(base + y1)) (overlaps in-flight tile load) ----
        compute_h(g_base + b * DH, yin + b * DH, gamma, beta, s_h, s_red, t);

        // ---- tile ready ----
        CP_WAIT0();
        __syncthreads();

        // ---- y2 rows: warp w computes row w of this chunk ----
        {
            float acc = 0.f;
            #pragma unroll
            for (int i = 0; i < 8; i++) {
                float4 v  = tile4[w * 256 + lane + i * 32];
                float4 hv = h4[lane + i * 32];
                acc += v.x * hv.x + v.y * hv.y + v.z * hv.z + v.w * hv.w;
            }
            #pragma unroll
            for (int o = 16; o > 0; o >>= 1)
                acc += __shfl_xor_sync(0xffffffffu, acc, o);
            if (lane == 0) {
                g_y0[b * DH + cb * F_ROWS + w] = acc;
                __threadfence();
            }
        }
        __syncthreads();

        // ---- arrive, then prefetch next tile BEFORE spinning ----
        if (t == 0) atomicAdd(&g_arrive[gang], 1);

        const int bn = b + F_GANGS;
        if (bn < BATCH) {
            const float* Abn = A + (size_t)bn * DH * DH + (size_t)(cb * F_ROWS) * DH;
            float* tn = tiles + (cur ^ 1) * F_TILE;
            #pragma unroll
            for (int k = 0; k < F_ROWS; k++)
                cp_async16(tn + k * DH + t * 4, Abn + k * DH + t * 4);
        }
        CP_COMMIT();

        // ---- gang barrier (monotonic counter) ----
        if (t == 0) {
            const int target = (iter + 1) * F_GANG_BLOCKS;
            while (atomicAdd(&g_arrive[gang], 0) < target)
                __nanosleep(32);
            __threadfence();
        }
        __syncthreads();

        // ---- h3 = relu(LN(base + y2)) ----
        compute_h(g_base + b * DH, g_y0 + b * DH, gamma, beta, s_h, s_red, t);

        if (cb == 0)
            reinterpret_cast<float4*>(outH + b * DH)[t] = h4[t];

        // ---- A_k rows from the smem tile (no second HBM read) ----
        float4* __restrict__ Ob =
            reinterpret_cast<float4*>(outA + (size_t)b * DH * DH) +
            (size_t)(cb * F_ROWS) * 256;
        const float4 hv = h4[t];
        #pragma unroll
        for (int r = 0; r < F_ROWS; r++) {
            const float hi = s_h[cb * F_ROWS + r] * ETA;
            float4 a = tile4[r * 256 + t];
            float4 o;
            o.x = fmaf(LAM, a.x, hi * hv.x);
            o.y = fmaf(LAM, a.y, hi * hv.y);
            o.z = fmaf(LAM, a.z, hi * hv.z);
            o.w = fmaf(LAM, a.w, hi * hv.w);
            __stcs(Ob + r * 256 + t, o);
        }
        // next iteration's compute_h syncthreads protects tile/s_h reuse
    }
}

// ---------------------------------------------------------------------------
extern "C" void kernel_launch(void* const* d_in, const int* in_sizes, int n_in,
                              void* d_out, int out_size)
{
    const float* z      = (const float*)d_in[0];
    const float* h_prev = (const float*)d_in[1];
    const float* A_prev = (const float*)d_in[2];
    const float* W_h    = (const float*)d_in[3];
    const float* W_g    = (const float*)d_in[4];
    const float* b_h    = (const float*)d_in[5];
    const float* gamma  = (const float*)d_in[6];
    const float* beta   = (const float*)d_in[7];

    float* outH = (float*)d_out;                 // h_t: 128*1024
    float* outA = (float*)d_out + BATCH * DH;    // A_k: 128*1024*1024

    float* y0;  cudaGetSymbolAddress((void**)&y0, g_y0);
    float* y1;  cudaGetSymbolAddress((void**)&y1, g_y1);

    cudaFuncSetAttribute(fused_mv3_update_kernel,
                         cudaFuncAttributeMaxDynamicSharedMemorySize,
                         (int)F_SMEM);

    base_gemm_kernel<<<dim3(BATCH / 32, DH / 32), 256>>>(h_prev, z, W_h, W_g, b_h);

    matvec_ln_kernel<<<dim3(16, BATCH), 256>>>(A_prev, nullptr, y0, gamma, beta);
    matvec_ln_kernel<<<dim3(16, BATCH), 256>>>(A_prev, y0,      y1, gamma, beta);

    fused_mv3_update_kernel<<<F_GRID, 256, F_SMEM>>>(
        A_prev, y1, gamma, beta, outH, outA);
}

// round 6
// speedup vs baseline: 1.0869x; 1.0869x over previous
#include <cuda_runtime.h>

#define BATCH 128
#define DG 512
#define DH 1024
#define LAM 0.95f
#define ETA 0.5f
#define LN_EPS 1e-5f

// Scratch (allocation-free)
__device__ float g_base[BATCH * DH];
__device__ float g_y0[BATCH * DH];
__device__ float g_y1[BATCH * DH];

// ---------------------------------------------------------------------------
// Kernel 1: base = h_prev@Wh^T + z@Wg^T + bh.
// ---------------------------------------------------------------------------
__global__ void base_gemm_kernel(const float* __restrict__ Hp,
                                 const float* __restrict__ Z,
                                 const float* __restrict__ Wh,
                                 const float* __restrict__ Wg,
                                 const float* __restrict__ bh)
{
    __shared__ float Hs[32][33];
    __shared__ float Ws[32][33];

    const int tid = threadIdx.x;
    const int tx = tid & 15;
    const int ty = tid >> 4;
    const int bm0 = blockIdx.x * 32;
    const int n0  = blockIdx.y * 32;

    float acc00 = 0.f, acc01 = 0.f, acc10 = 0.f, acc11 = 0.f;

    for (int k0 = 0; k0 < DH + DG; k0 += 32) {
        const float* src;
        const float* wsrc;
        int K, kk0;
        if (k0 < DH) { src = Hp; wsrc = Wh; K = DH; kk0 = k0; }
        else         { src = Z;  wsrc = Wg; K = DG; kk0 = k0 - DH; }

        #pragma unroll
        for (int l = 0; l < 4; l++) {
            int idx = tid + l * 256;
            int r = idx >> 5, c = idx & 31;
            Hs[r][c] = src[(bm0 + r) * K + kk0 + c];
            Ws[r][c] = wsrc[(n0 + r) * K + kk0 + c];
        }
        __syncthreads();

        #pragma unroll
        for (int kk = 0; kk < 32; kk++) {
            float h0 = Hs[ty * 2][kk];
            float h1 = Hs[ty * 2 + 1][kk];
            float w0 = Ws[tx * 2][kk];
            float w1 = Ws[tx * 2 + 1][kk];
            acc00 += h0 * w0; acc01 += h0 * w1;
            acc10 += h1 * w0; acc11 += h1 * w1;
        }
        __syncthreads();
    }

    const int r0 = bm0 + ty * 2;
    const int c0 = n0 + tx * 2;
    const float bias0 = bh[c0];
    const float bias1 = bh[c0 + 1];
    g_base[r0 * DH + c0]           = acc00 + bias0;
    g_base[r0 * DH + c0 + 1]       = acc01 + bias1;
    g_base[(r0 + 1) * DH + c0]     = acc10 + bias0;
    g_base[(r0 + 1) * DH + c0 + 1] = acc11 + bias1;
}

// ---------------------------------------------------------------------------
// In-block LN+ReLU: 256 threads, h[b] (1024 floats) into s_h. Trailing sync.
// ---------------------------------------------------------------------------
__device__ __forceinline__ void compute_h(const float* __restrict__ base_b,
                                          const float* __restrict__ y_b,
                                          const float* __restrict__ gamma,
                                          const float* __restrict__ beta,
                                          float* __restrict__ s_h,
                                          float* __restrict__ s_red,
                                          int t)
{
    const int w = t >> 5, lane = t & 31;

    float4 x = reinterpret_cast<const float4*>(base_b)[t];
    if (y_b) {
        float4 y = reinterpret_cast<const float4*>(y_b)[t];
        x.x += y.x; x.y += y.y; x.z += y.z; x.w += y.w;
    }
    float s  = (x.x + x.y) + (x.z + x.w);
    float ss = fmaf(x.x, x.x, x.y * x.y) + fmaf(x.z, x.z, x.w * x.w);

    #pragma unroll
    for (int o = 16; o > 0; o >>= 1) {
        s  += __shfl_xor_sync(0xffffffffu, s,  o);
        ss += __shfl_xor_sync(0xffffffffu, ss, o);
    }
    if (lane == 0) { s_red[w] = s; s_red[8 + w] = ss; }
    __syncthreads();
    if (t < 32) {
        float a = (lane < 8) ? s_red[lane]     : 0.f;
        float c = (lane < 8) ? s_red[8 + lane] : 0.f;
        #pragma unroll
        for (int o = 4; o > 0; o >>= 1) {
            a += __shfl_xor_sync(0xffffffffu, a, o);
            c += __shfl_xor_sync(0xffffffffu, c, o);
        }
        if (lane == 0) { s_red[0] = a; s_red[1] = c; }
    }
    __syncthreads();

    const float mu   = s_red[0] * (1.0f / DH);
    const float var  = s_red[1] * (1.0f / DH) - mu * mu;
    const float rstd = rsqrtf(var + LN_EPS);

    float4 g  = reinterpret_cast<const float4*>(gamma)[t];
    float4 be = reinterpret_cast<const float4*>(beta)[t];
    float4 h;
    h.x = fmaxf(0.f, (x.x - mu) * rstd * g.x + be.x);
    h.y = fmaxf(0.f, (x.y - mu) * rstd * g.y + be.y);
    h.z = fmaxf(0.f, (x.z - mu) * rstd * g.z + be.z);
    h.w = fmaxf(0.f, (x.w - mu) * rstd * g.w + be.w);
    reinterpret_cast<float4*>(s_h)[t] = h;
    __syncthreads();
}

// ---------------------------------------------------------------------------
// Kernel 2 (x3): h = relu(LN(base [+ yin])), then yout = A@h.
// 4 rows interleaved per warp -> 8 independent LDG.128 in flight.
// grid = (16 chunks, 128 batches), 256 thr.
// ---------------------------------------------------------------------------
__global__ __launch_bounds__(256)
void matvec_ln_kernel(const float* __restrict__ A,
                      const float* __restrict__ yin,    // may be null
                      float* __restrict__ yout,
                      const float* __restrict__ gamma,
                      const float* __restrict__ beta)
{
    __shared__ float s_h[DH];
    __shared__ float s_red[16];

    const int b = blockIdx.y;
    const int chunk = blockIdx.x;
    const int t = threadIdx.x;
    const int w = t >> 5, lane = t & 31;

    compute_h(g_base + b * DH, yin ? yin + b * DH : nullptr,
              gamma, beta, s_h, s_red, t);

    const float4* __restrict__ Ab =
        reinterpret_cast<const float4*>(A + (size_t)b * DH * DH);
    const float4* h4 = reinterpret_cast<const float4*>(s_h);

    #pragma unroll
    for (int g = 0; g < 2; g++) {
        const int r0 = chunk * 64 + w * 8 + g * 4;
        const float4* Ar0 = Ab + (size_t)r0 * 256;
        const float4* Ar1 = Ar0 + 256;
        const float4* Ar2 = Ar0 + 512;
        const float4* Ar3 = Ar0 + 768;

        float a0 = 0.f, a1 = 0.f, a2 = 0.f, a3 = 0.f;
        #pragma unroll
        for (int it = 0; it < 8; it++) {
            float4 v0 = __ldcs(Ar0 + lane + it * 32);
            float4 v1 = __ldcs(Ar1 + lane + it * 32);
            float4 v2 = __ldcs(Ar2 + lane + it * 32);
            float4 v3 = __ldcs(Ar3 + lane + it * 32);
            float4 hv = h4[lane + it * 32];
            a0 += v0.x * hv.x + v0.y * hv.y + v0.z * hv.z + v0.w * hv.w;
            a1 += v1.x * hv.x + v1.y * hv.y + v1.z * hv.z + v1.w * hv.w;
            a2 += v2.x * hv.x + v2.y * hv.y + v2.z * hv.z + v2.w * hv.w;
            a3 += v3.x * hv.x + v3.y * hv.y + v3.z * hv.z + v3.w * hv.w;
        }
        #pragma unroll
        for (int o = 16; o > 0; o >>= 1) {
            a0 += __shfl_xor_sync(0xffffffffu, a0, o);
            a1 += __shfl_xor_sync(0xffffffffu, a1, o);
            a2 += __shfl_xor_sync(0xffffffffu, a2, o);
            a3 += __shfl_xor_sync(0xffffffffu, a3, o);
        }
        if (lane == 0) {
            yout[b * DH + r0]     = a0;
            yout[b * DH + r0 + 1] = a1;
            yout[b * DH + r0 + 2] = a2;
            yout[b * DH + r0 + 3] = a3;
        }
    }
}

// ---------------------------------------------------------------------------
// Kernel 3: h3 = relu(LN(base + yin)) written straight into outH (the h_t
// output), which then feeds the streaming update. grid=128, 256 thr.
// ---------------------------------------------------------------------------
__global__ __launch_bounds__(256)
void h_final_kernel(const float* __restrict__ yin,
                    const float* __restrict__ gamma,
                    const float* __restrict__ beta,
                    float* __restrict__ outH)
{
    __shared__ float s_h[DH];
    __shared__ float s_red[16];
    const int b = blockIdx.x;
    const int t = threadIdx.x;

    compute_h(g_base + b * DH, yin + b * DH, gamma, beta, s_h, s_red, t);
    reinterpret_cast<float4*>(outH + b * DH)[t] =
        reinterpret_cast<const float4*>(s_h)[t];
}

// ---------------------------------------------------------------------------
// Kernel 4: pure-stream Hebbian update. No smem, no barriers.
// A_k = LAM*A + ETA*h3 h3^T, h3 read from outH via __ldg (L2/L1 resident).
// grid = (64 chunks of 16 rows, 128 batches), 256 thr.
// Register ping-pong: 4 rows in flight while previous 4 store.
// ---------------------------------------------------------------------------
__global__ __launch_bounds__(256)
void update_stream_kernel(const float* __restrict__ A,
                          const float* __restrict__ h3,   // = outH
                          float* __restrict__ outA)
{
    const int b = blockIdx.y;
    const int chunk = blockIdx.x;
    const int t = threadIdx.x;
    const int row0 = chunk * 16;

    const float4* __restrict__ Ab =
        reinterpret_cast<const float4*>(A + (size_t)b * DH * DH) +
        (size_t)row0 * 256;
    float4* __restrict__ Ob =
        reinterpret_cast<float4*>(outA + (size_t)b * DH * DH) +
        (size_t)row0 * 256;

    const float4 hv = __ldg(reinterpret_cast<const float4*>(h3 + b * DH) + t);

    float hr[16];
    #pragma unroll
    for (int r = 0; r < 16; r++)
        hr[r] = __ldg(h3 + b * DH + row0 + r) * ETA;

    // software-pipelined stream: group of 4 rows in flight
    float4 c0 = __ldcs(Ab + 0 * 256 + t);
    float4 c1 = __ldcs(Ab + 1 * 256 + t);
    float4 c2 = __ldcs(Ab + 2 * 256 + t);
    float4 c3 = __ldcs(Ab + 3 * 256 + t);

    #pragma unroll
    for (int g = 0; g < 4; g++) {
        float4 n0, n1, n2, n3;
        if (g < 3) {
            const float4* An = Ab + (size_t)(g + 1) * 4 * 256 + t;
            n0 = __ldcs(An + 0 * 256);
            n1 = __ldcs(An + 1 * 256);
            n2 = __ldcs(An + 2 * 256);
            n3 = __ldcs(An + 3 * 256);
        }
        float4* Og = Ob + (size_t)g * 4 * 256 + t;
        const float h0 = hr[g * 4 + 0];
        const float h1 = hr[g * 4 + 1];
        const float h2 = hr[g * 4 + 2];
        const float h3v = hr[g * 4 + 3];
        float4 o;
        o.x = fmaf(LAM, c0.x, h0 * hv.x); o.y = fmaf(LAM, c0.y, h0 * hv.y);
        o.z = fmaf(LAM, c0.z, h0 * hv.z); o.w = fmaf(LAM, c0.w, h0 * hv.w);
        __stcs(Og + 0 * 256, o);
        o.x = fmaf(LAM, c1.x, h1 * hv.x); o.y = fmaf(LAM, c1.y, h1 * hv.y);
        o.z = fmaf(LAM, c1.z, h1 * hv.z); o.w = fmaf(LAM, c1.w, h1 * hv.w);
        __stcs(Og + 1 * 256, o);
        o.x = fmaf(LAM, c2.x, h2 * hv.x); o.y = fmaf(LAM, c2.y, h2 * hv.y);
        o.z = fmaf(LAM, c2.z, h2 * hv.z); o.w = fmaf(LAM, c2.w, h2 * hv.w);
        __stcs(Og + 2 * 256, o);
        o.x = fmaf(LAM, c3.x, h3v * hv.x); o.y = fmaf(LAM, c3.y, h3v * hv.y);
        o.z = fmaf(LAM, c3.z, h3v * hv.z); o.w = fmaf(LAM, c3.w, h3v * hv.w);
        __stcs(Og + 3 * 256, o);
        c0 = n0; c1 = n1; c2 = n2; c3 = n3;
    }
}

// ---------------------------------------------------------------------------
extern "C" void kernel_launch(void* const* d_in, const int* in_sizes, int n_in,
                              void* d_out, int out_size)
{
    const float* z      = (const float*)d_in[0];
    const float* h_prev = (const float*)d_in[1];
    const float* A_prev = (const float*)d_in[2];
    const float* W_h    = (const float*)d_in[3];
    const float* W_g    = (const float*)d_in[4];
    const float* b_h    = (const float*)d_in[5];
    const float* gamma  = (const float*)d_in[6];
    const float* beta   = (const float*)d_in[7];

    float* outH = (float*)d_out;                 // h_t: 128*1024
    float* outA = (float*)d_out + BATCH * DH;    // A_k: 128*1024*1024

    float* y0;  cudaGetSymbolAddress((void**)&y0, g_y0);
    float* y1;  cudaGetSymbolAddress((void**)&y1, g_y1);

    base_gemm_kernel<<<dim3(BATCH / 32, DH / 32), 256>>>(h_prev, z, W_h, W_g, b_h);

    matvec_ln_kernel<<<dim3(16, BATCH), 256>>>(A_prev, nullptr, y0, gamma, beta);
    matvec_ln_kernel<<<dim3(16, BATCH), 256>>>(A_prev, y0,      y1, gamma, beta);
    matvec_ln_kernel<<<dim3(16, BATCH), 256>>>(A_prev, y1,      y0, gamma, beta);

    h_final_kernel<<<BATCH, 256>>>(y0, gamma, beta, outH);
    update_stream_kernel<<<dim3(64, BATCH), 256>>>(A_prev, outH, outA);
}

// round 7
// speedup vs baseline: 1.1950x; 1.0994x over previous
#include <cuda_runtime.h>
#include <cuda_fp16.h>

#define BATCH 128
#define DG 512
#define DH 1024
#define LAM 0.95f
#define ETA 0.5f
#define LN_EPS 1e-5f

// Scratch (allocation-free)
__device__ float  g_base[BATCH * DH];
__device__ float  g_y0[BATCH * DH];
__device__ float  g_y1[BATCH * DH];
__device__ __half g_Ah[(size_t)BATCH * DH * DH];   // fp16 copy of A (268MB)

// ---------------------------------------------------------------------------
__device__ __forceinline__ float2 pack_h4(float4 v) {
    __half2 a = __floats2half2_rn(v.x, v.y);
    __half2 b = __floats2half2_rn(v.z, v.w);
    float2 r;
    r.x = __uint_as_float(*reinterpret_cast<unsigned int*>(&a));
    r.y = __uint_as_float(*reinterpret_cast<unsigned int*>(&b));
    return r;
}

__device__ __forceinline__ float dot8(uint4 v, float4 ha, float4 hb) {
    const __half2* p = reinterpret_cast<const __half2*>(&v);
    float2 f0 = __half22float2(p[0]);
    float2 f1 = __half22float2(p[1]);
    float2 f2 = __half22float2(p[2]);
    float2 f3 = __half22float2(p[3]);
    return f0.x * ha.x + f0.y * ha.y + f1.x * ha.z + f1.y * ha.w
         + f2.x * hb.x + f2.y * hb.y + f3.x * hb.z + f3.y * hb.w;
}

// ---------------------------------------------------------------------------
// Kernel 1: base = h_prev@Wh^T + z@Wg^T + bh.
// ---------------------------------------------------------------------------
__global__ void base_gemm_kernel(const float* __restrict__ Hp,
                                 const float* __restrict__ Z,
                                 const float* __restrict__ Wh,
                                 const float* __restrict__ Wg,
                                 const float* __restrict__ bh)
{
    __shared__ float Hs[32][33];
    __shared__ float Ws[32][33];

    const int tid = threadIdx.x;
    const int tx = tid & 15;
    const int ty = tid >> 4;
    const int bm0 = blockIdx.x * 32;
    const int n0  = blockIdx.y * 32;

    float acc00 = 0.f, acc01 = 0.f, acc10 = 0.f, acc11 = 0.f;

    for (int k0 = 0; k0 < DH + DG; k0 += 32) {
        const float* src;
        const float* wsrc;
        int K, kk0;
        if (k0 < DH) { src = Hp; wsrc = Wh; K = DH; kk0 = k0; }
        else         { src = Z;  wsrc = Wg; K = DG; kk0 = k0 - DH; }

        #pragma unroll
        for (int l = 0; l < 4; l++) {
            int idx = tid + l * 256;
            int r = idx >> 5, c = idx & 31;
            Hs[r][c] = src[(bm0 + r) * K + kk0 + c];
            Ws[r][c] = wsrc[(n0 + r) * K + kk0 + c];
        }
        __syncthreads();

        #pragma unroll
        for (int kk = 0; kk < 32; kk++) {
            float h0 = Hs[ty * 2][kk];
            float h1 = Hs[ty * 2 + 1][kk];
            float w0 = Ws[tx * 2][kk];
            float w1 = Ws[tx * 2 + 1][kk];
            acc00 += h0 * w0; acc01 += h0 * w1;
            acc10 += h1 * w0; acc11 += h1 * w1;
        }
        __syncthreads();
    }

    const int r0 = bm0 + ty * 2;
    const int c0 = n0 + tx * 2;
    const float bias0 = bh[c0];
    const float bias1 = bh[c0 + 1];
    g_base[r0 * DH + c0]           = acc00 + bias0;
    g_base[r0 * DH + c0 + 1]       = acc01 + bias1;
    g_base[(r0 + 1) * DH + c0]     = acc10 + bias0;
    g_base[(r0 + 1) * DH + c0 + 1] = acc11 + bias1;
}

// ---------------------------------------------------------------------------
// In-block LN+ReLU: 256 threads, h[b] (1024 floats) into s_h. Trailing sync.
// ---------------------------------------------------------------------------
__device__ __forceinline__ void compute_h(const float* __restrict__ base_b,
                                          const float* __restrict__ y_b,
                                          const float* __restrict__ gamma,
                                          const float* __restrict__ beta,
                                          float* __restrict__ s_h,
                                          float* __restrict__ s_red,
                                          int t)
{
    const int w = t >> 5, lane = t & 31;

    float4 x = reinterpret_cast<const float4*>(base_b)[t];
    if (y_b) {
        float4 y = reinterpret_cast<const float4*>(y_b)[t];
        x.x += y.x; x.y += y.y; x.z += y.z; x.w += y.w;
    }
    float s  = (x.x + x.y) + (x.z + x.w);
    float ss = fmaf(x.x, x.x, x.y * x.y) + fmaf(x.z, x.z, x.w * x.w);

    #pragma unroll
    for (int o = 16; o > 0; o >>= 1) {
        s  += __shfl_xor_sync(0xffffffffu, s,  o);
        ss += __shfl_xor_sync(0xffffffffu, ss, o);
    }
    if (lane == 0) { s_red[w] = s; s_red[8 + w] = ss; }
    __syncthreads();
    if (t < 32) {
        float a = (lane < 8) ? s_red[lane]     : 0.f;
        float c = (lane < 8) ? s_red[8 + lane] : 0.f;
        #pragma unroll
        for (int o = 4; o > 0; o >>= 1) {
            a += __shfl_xor_sync(0xffffffffu, a, o);
            c += __shfl_xor_sync(0xffffffffu, c, o);
        }
        if (lane == 0) { s_red[0] = a; s_red[1] = c; }
    }
    __syncthreads();

    const float mu   = s_red[0] * (1.0f / DH);
    const float var  = s_red[1] * (1.0f / DH) - mu * mu;
    const float rstd = rsqrtf(var + LN_EPS);

    float4 g  = reinterpret_cast<const float4*>(gamma)[t];
    float4 be = reinterpret_cast<const float4*>(beta)[t];
    float4 h;
    h.x = fmaxf(0.f, (x.x - mu) * rstd * g.x + be.x);
    h.y = fmaxf(0.f, (x.y - mu) * rstd * g.y + be.y);
    h.z = fmaxf(0.f, (x.z - mu) * rstd * g.z + be.z);
    h.w = fmaxf(0.f, (x.w - mu) * rstd * g.w + be.w);
    reinterpret_cast<float4*>(s_h)[t] = h;
    __syncthreads();
}

// ---------------------------------------------------------------------------
// Kernel 2: mv1 + fp16 conversion.
// h1 = relu(LN(base)); y = A@h1 in fp32; stream fp16 copy of A to g_Ah.
// grid = (16 chunks, 128 batches), 256 thr, 4 rows/warp interleaved.
// ---------------------------------------------------------------------------
__global__ __launch_bounds__(256)
void matvec_conv_kernel(const float* __restrict__ A,
                        float* __restrict__ yout,
                        const float* __restrict__ gamma,
                        const float* __restrict__ beta)
{
    __shared__ float s_h[DH];
    __shared__ float s_red[16];

    const int b = blockIdx.y;
    const int chunk = blockIdx.x;
    const int t = threadIdx.x;
    const int w = t >> 5, lane = t & 31;

    compute_h(g_base + b * DH, nullptr, gamma, beta, s_h, s_red, t);

    const float4* __restrict__ Ab =
        reinterpret_cast<const float4*>(A + (size_t)b * DH * DH);
    const float4* h4 = reinterpret_cast<const float4*>(s_h);

    #pragma unroll
    for (int g = 0; g < 2; g++) {
        const int r0 = chunk * 64 + w * 8 + g * 4;
        const float4* Ar0 = Ab + (size_t)r0 * 256;
        float2* __restrict__ Oh0 =
            reinterpret_cast<float2*>(g_Ah + ((size_t)b * DH + r0) * DH);

        float a0 = 0.f, a1 = 0.f, a2 = 0.f, a3 = 0.f;
        #pragma unroll
        for (int it = 0; it < 8; it++) {
            float4 v0 = __ldcs(Ar0 + lane + it * 32);
            float4 v1 = __ldcs(Ar0 + 256 + lane + it * 32);
            float4 v2 = __ldcs(Ar0 + 512 + lane + it * 32);
            float4 v3 = __ldcs(Ar0 + 768 + lane + it * 32);
            float4 hv = h4[lane + it * 32];
            a0 += v0.x * hv.x + v0.y * hv.y + v0.z * hv.z + v0.w * hv.w;
            a1 += v1.x * hv.x + v1.y * hv.y + v1.z * hv.z + v1.w * hv.w;
            a2 += v2.x * hv.x + v2.y * hv.y + v2.z * hv.z + v2.w * hv.w;
            a3 += v3.x * hv.x + v3.y * hv.y + v3.z * hv.z + v3.w * hv.w;
            __stcs(Oh0 + lane + it * 32,       pack_h4(v0));
            __stcs(Oh0 + 256 + lane + it * 32, pack_h4(v1));
            __stcs(Oh0 + 512 + lane + it * 32, pack_h4(v2));
            __stcs(Oh0 + 768 + lane + it * 32, pack_h4(v3));
        }
        #pragma unroll
        for (int o = 16; o > 0; o >>= 1) {
            a0 += __shfl_xor_sync(0xffffffffu, a0, o);
            a1 += __shfl_xor_sync(0xffffffffu, a1, o);
            a2 += __shfl_xor_sync(0xffffffffu, a2, o);
            a3 += __shfl_xor_sync(0xffffffffu, a3, o);
        }
        if (lane == 0) {
            yout[b * DH + r0]     = a0;
            yout[b * DH + r0 + 1] = a1;
            yout[b * DH + r0 + 2] = a2;
            yout[b * DH + r0 + 3] = a3;
        }
    }
}

// ---------------------------------------------------------------------------
// Kernel 3 (x2): fp16 matvec. h = relu(LN(base + yin)); yout = Ah@h.
// Each row = 1024 halfs = 128 uint4; warp covers a row in 4 iters.
// grid = (16 chunks, 128 batches), 256 thr, 4 rows/warp interleaved.
// ---------------------------------------------------------------------------
__global__ __launch_bounds__(256)
void matvec_h_kernel(const float* __restrict__ yin,
                     float* __restrict__ yout,
                     const float* __restrict__ gamma,
                     const float* __restrict__ beta)
{
    __shared__ float s_h[DH];
    __shared__ float s_red[16];

    const int b = blockIdx.y;
    const int chunk = blockIdx.x;
    const int t = threadIdx.x;
    const int w = t >> 5, lane = t & 31;

    compute_h(g_base + b * DH, yin + b * DH, gamma, beta, s_h, s_red, t);

    const float4* h4 = reinterpret_cast<const float4*>(s_h);

    #pragma unroll
    for (int g = 0; g < 2; g++) {
        const int r0 = chunk * 64 + w * 8 + g * 4;
        const uint4* __restrict__ R0 =
            reinterpret_cast<const uint4*>(g_Ah + ((size_t)b * DH + r0) * DH);

        float a0 = 0.f, a1 = 0.f, a2 = 0.f, a3 = 0.f;
        #pragma unroll
        for (int it = 0; it < 4; it++) {
            uint4 v0 = __ldcs(R0 + lane + it * 32);
            uint4 v1 = __ldcs(R0 + 128 + lane + it * 32);
            uint4 v2 = __ldcs(R0 + 256 + lane + it * 32);
            uint4 v3 = __ldcs(R0 + 384 + lane + it * 32);
            const int idx = (it * 32 + lane) * 2;
            float4 ha = h4[idx];
            float4 hb = h4[idx + 1];
            a0 += dot8(v0, ha, hb);
            a1 += dot8(v1, ha, hb);
            a2 += dot8(v2, ha, hb);
            a3 += dot8(v3, ha, hb);
        }
        #pragma unroll
        for (int o = 16; o > 0; o >>= 1) {
            a0 += __shfl_xor_sync(0xffffffffu, a0, o);
            a1 += __shfl_xor_sync(0xffffffffu, a1, o);
            a2 += __shfl_xor_sync(0xffffffffu, a2, o);
            a3 += __shfl_xor_sync(0xffffffffu, a3, o);
        }
        if (lane == 0) {
            yout[b * DH + r0]     = a0;
            yout[b * DH + r0 + 1] = a1;
            yout[b * DH + r0 + 2] = a2;
            yout[b * DH + r0 + 3] = a3;
        }
    }
}

// ---------------------------------------------------------------------------
// Kernel 4: h3 = relu(LN(base + yin)) written straight into outH.
// ---------------------------------------------------------------------------
__global__ __launch_bounds__(256)
void h_final_kernel(const float* __restrict__ yin,
                    const float* __restrict__ gamma,
                    const float* __restrict__ beta,
                    float* __restrict__ outH)
{
    __shared__ float s_h[DH];
    __shared__ float s_red[16];
    const int b = blockIdx.x;
    const int t = threadIdx.x;

    compute_h(g_base + b * DH, yin + b * DH, gamma, beta, s_h, s_red, t);
    reinterpret_cast<float4*>(outH + b * DH)[t] =
        reinterpret_cast<const float4*>(s_h)[t];
}

// ---------------------------------------------------------------------------
// Kernel 5: pure-stream Hebbian update (fp32 A). No smem, no barriers.
// ---------------------------------------------------------------------------
__global__ __launch_bounds__(256)
void update_stream_kernel(const float* __restrict__ A,
                          const float* __restrict__ h3,   // = outH
                          float* __restrict__ outA)
{
    const int b = blockIdx.y;
    const int chunk = blockIdx.x;
    const int t = threadIdx.x;
    const int row0 = chunk * 16;

    const float4* __restrict__ Ab =
        reinterpret_cast<const float4*>(A + (size_t)b * DH * DH) +
        (size_t)row0 * 256;
    float4* __restrict__ Ob =
        reinterpret_cast<float4*>(outA + (size_t)b * DH * DH) +
        (size_t)row0 * 256;

    const float4 hv = __ldg(reinterpret_cast<const float4*>(h3 + b * DH) + t);

    float hr[16];
    #pragma unroll
    for (int r = 0; r < 16; r++)
        hr[r] = __ldg(h3 + b * DH + row0 + r) * ETA;

    float4 c0 = __ldcs(Ab + 0 * 256 + t);
    float4 c1 = __ldcs(Ab + 1 * 256 + t);
    float4 c2 = __ldcs(Ab + 2 * 256 + t);
    float4 c3 = __ldcs(Ab + 3 * 256 + t);

    #pragma unroll
    for (int g = 0; g < 4; g++) {
        float4 n0, n1, n2, n3;
        if (g < 3) {
            const float4* An = Ab + (size_t)(g + 1) * 4 * 256 + t;
            n0 = __ldcs(An + 0 * 256);
            n1 = __ldcs(An + 1 * 256);
            n2 = __ldcs(An + 2 * 256);
            n3 = __ldcs(An + 3 * 256);
        }
        float4* Og = Ob + (size_t)g * 4 * 256 + t;
        const float h0 = hr[g * 4 + 0];
        const float h1 = hr[g * 4 + 1];
        const float h2 = hr[g * 4 + 2];
        const float h3v = hr[g * 4 + 3];
        float4 o;
        o.x = fmaf(LAM, c0.x, h0 * hv.x); o.y = fmaf(LAM, c0.y, h0 * hv.y);
        o.z = fmaf(LAM, c0.z, h0 * hv.z); o.w = fmaf(LAM, c0.w, h0 * hv.w);
        __stcs(Og + 0 * 256, o);
        o.x = fmaf(LAM, c1.x, h1 * hv.x); o.y = fmaf(LAM, c1.y, h1 * hv.y);
        o.z = fmaf(LAM, c1.z, h1 * hv.z); o.w = fmaf(LAM, c1.w, h1 * hv.w);
        __stcs(Og + 1 * 256, o);
        o.x = fmaf(LAM, c2.x, h2 * hv.x); o.y = fmaf(LAM, c2.y, h2 * hv.y);
        o.z = fmaf(LAM, c2.z, h2 * hv.z); o.w = fmaf(LAM, c2.w, h2 * hv.w);
        __stcs(Og + 2 * 256, o);
        o.x = fmaf(LAM, c3.x, h3v * hv.x); o.y = fmaf(LAM, c3.y, h3v * hv.y);
        o.z = fmaf(LAM, c3.z, h3v * hv.z); o.w = fmaf(LAM, c3.w, h3v * hv.w);
        __stcs(Og + 3 * 256, o);
        c0 = n0; c1 = n1; c2 = n2; c3 = n3;
    }
}

// ---------------------------------------------------------------------------
extern "C" void kernel_launch(void* const* d_in, const int* in_sizes, int n_in,
                              void* d_out, int out_size)
{
    const float* z      = (const float*)d_in[0];
    const float* h_prev = (const float*)d_in[1];
    const float* A_prev = (const float*)d_in[2];
    const float* W_h    = (const float*)d_in[3];
    const float* W_g    = (const float*)d_in[4];
    const float* b_h    = (const float*)d_in[5];
    const float* gamma  = (const float*)d_in[6];
    const float* beta   = (const float*)d_in[7];

    float* outH = (float*)d_out;                 // h_t: 128*1024
    float* outA = (float*)d_out + BATCH * DH;    // A_k: 128*1024*1024

    float* y0;  cudaGetSymbolAddress((void**)&y0, g_y0);
    float* y1;  cudaGetSymbolAddress((void**)&y1, g_y1);

    base_gemm_kernel<<<dim3(BATCH / 32, DH / 32), 256>>>(h_prev, z, W_h, W_g, b_h);

    matvec_conv_kernel<<<dim3(16, BATCH), 256>>>(A_prev, y0, gamma, beta);
    matvec_h_kernel<<<dim3(16, BATCH), 256>>>(y0, y1, gamma, beta);
    matvec_h_kernel<<<dim3(16, BATCH), 256>>>(y1, y0, gamma, beta);

    h_final_kernel<<<BATCH, 256>>>(y0, gamma, beta, outH);
    update_stream_kernel<<<dim3(64, BATCH), 256>>>(A_prev, outH, outA);
}

// round 8
// speedup vs baseline: 1.2921x; 1.0813x over previous
#include <cuda_runtime.h>
#include <cuda_fp16.h>

#define BATCH 128
#define DG 512
#define DH 1024
#define LAM 0.95f
#define ETA 0.5f
#define LN_EPS 1e-5f

// Scratch (allocation-free)
__device__ float  g_base[BATCH * DH];
__device__ float  g_y0[BATCH * DH];
__device__ float  g_y1[BATCH * DH];
__device__ __half g_Ah[(size_t)BATCH * DH * DH];   // fp16 copy of A (268MB)

// ---------------------------------------------------------------------------
__device__ __forceinline__ float2 pack_h4(float4 v) {
    __half2 a = __floats2half2_rn(v.x, v.y);
    __half2 b = __floats2half2_rn(v.z, v.w);
    float2 r;
    r.x = __uint_as_float(*reinterpret_cast<unsigned int*>(&a));
    r.y = __uint_as_float(*reinterpret_cast<unsigned int*>(&b));
    return r;
}

__device__ __forceinline__ float dot8(uint4 v, float4 ha, float4 hb) {
    const __half2* p = reinterpret_cast<const __half2*>(&v);
    float2 f0 = __half22float2(p[0]);
    float2 f1 = __half22float2(p[1]);
    float2 f2 = __half22float2(p[2]);
    float2 f3 = __half22float2(p[3]);
    return f0.x * ha.x + f0.y * ha.y + f1.x * ha.z + f1.y * ha.w
         + f2.x * hb.x + f2.y * hb.y + f3.x * hb.z + f3.y * hb.w;
}

// unpack 4 halfs (uint2) to float4
__device__ __forceinline__ float4 unpack_h4(uint2 v) {
    __half2 lo = *reinterpret_cast<__half2*>(&v.x);
    __half2 hi = *reinterpret_cast<__half2*>(&v.y);
    float2 f0 = __half22float2(lo);
    float2 f1 = __half22float2(hi);
    float4 r; r.x = f0.x; r.y = f0.y; r.z = f1.x; r.w = f1.y;
    return r;
}

// ---------------------------------------------------------------------------
// Kernel 1: base = h_prev@Wh^T + z@Wg^T + bh.
// ---------------------------------------------------------------------------
__global__ void base_gemm_kernel(const float* __restrict__ Hp,
                                 const float* __restrict__ Z,
                                 const float* __restrict__ Wh,
                                 const float* __restrict__ Wg,
                                 const float* __restrict__ bh)
{
    __shared__ float Hs[32][33];
    __shared__ float Ws[32][33];

    const int tid = threadIdx.x;
    const int tx = tid & 15;
    const int ty = tid >> 4;
    const int bm0 = blockIdx.x * 32;
    const int n0  = blockIdx.y * 32;

    float acc00 = 0.f, acc01 = 0.f, acc10 = 0.f, acc11 = 0.f;

    for (int k0 = 0; k0 < DH + DG; k0 += 32) {
        const float* src;
        const float* wsrc;
        int K, kk0;
        if (k0 < DH) { src = Hp; wsrc = Wh; K = DH; kk0 = k0; }
        else         { src = Z;  wsrc = Wg; K = DG; kk0 = k0 - DH; }

        #pragma unroll
        for (int l = 0; l < 4; l++) {
            int idx = tid + l * 256;
            int r = idx >> 5, c = idx & 31;
            Hs[r][c] = src[(bm0 + r) * K + kk0 + c];
            Ws[r][c] = wsrc[(n0 + r) * K + kk0 + c];
        }
        __syncthreads();

        #pragma unroll
        for (int kk = 0; kk < 32; kk++) {
            float h0 = Hs[ty * 2][kk];
            float h1 = Hs[ty * 2 + 1][kk];
            float w0 = Ws[tx * 2][kk];
            float w1 = Ws[tx * 2 + 1][kk];
            acc00 += h0 * w0; acc01 += h0 * w1;
            acc10 += h1 * w0; acc11 += h1 * w1;
        }
        __syncthreads();
    }

    const int r0 = bm0 + ty * 2;
    const int c0 = n0 + tx * 2;
    const float bias0 = bh[c0];
    const float bias1 = bh[c0 + 1];
    g_base[r0 * DH + c0]           = acc00 + bias0;
    g_base[r0 * DH + c0 + 1]       = acc01 + bias1;
    g_base[(r0 + 1) * DH + c0]     = acc10 + bias0;
    g_base[(r0 + 1) * DH + c0 + 1] = acc11 + bias1;
}

// ---------------------------------------------------------------------------
// In-block LN+ReLU: 256 threads, h[b] (1024 floats) into s_h. Trailing sync.
// ---------------------------------------------------------------------------
__device__ __forceinline__ void compute_h(const float* __restrict__ base_b,
                                          const float* __restrict__ y_b,
                                          const float* __restrict__ gamma,
                                          const float* __restrict__ beta,
                                          float* __restrict__ s_h,
                                          float* __restrict__ s_red,
                                          int t)
{
    const int w = t >> 5, lane = t & 31;

    float4 x = reinterpret_cast<const float4*>(base_b)[t];
    if (y_b) {
        float4 y = reinterpret_cast<const float4*>(y_b)[t];
        x.x += y.x; x.y += y.y; x.z += y.z; x.w += y.w;
    }
    float s  = (x.x + x.y) + (x.z + x.w);
    float ss = fmaf(x.x, x.x, x.y * x.y) + fmaf(x.z, x.z, x.w * x.w);

    #pragma unroll
    for (int o = 16; o > 0; o >>= 1) {
        s  += __shfl_xor_sync(0xffffffffu, s,  o);
        ss += __shfl_xor_sync(0xffffffffu, ss, o);
    }
    if (lane == 0) { s_red[w] = s; s_red[8 + w] = ss; }
    __syncthreads();
    if (t < 32) {
        float a = (lane < 8) ? s_red[lane]     : 0.f;
        float c = (lane < 8) ? s_red[8 + lane] : 0.f;
        #pragma unroll
        for (int o = 4; o > 0; o >>= 1) {
            a += __shfl_xor_sync(0xffffffffu, a, o);
            c += __shfl_xor_sync(0xffffffffu, c, o);
        }
        if (lane == 0) { s_red[0] = a; s_red[1] = c; }
    }
    __syncthreads();

    const float mu   = s_red[0] * (1.0f / DH);
    const float var  = s_red[1] * (1.0f / DH) - mu * mu;
    const float rstd = rsqrtf(var + LN_EPS);

    float4 g  = reinterpret_cast<const float4*>(gamma)[t];
    float4 be = reinterpret_cast<const float4*>(beta)[t];
    float4 h;
    h.x = fmaxf(0.f, (x.x - mu) * rstd * g.x + be.x);
    h.y = fmaxf(0.f, (x.y - mu) * rstd * g.y + be.y);
    h.z = fmaxf(0.f, (x.z - mu) * rstd * g.z + be.z);
    h.w = fmaxf(0.f, (x.w - mu) * rstd * g.w + be.w);
    reinterpret_cast<float4*>(s_h)[t] = h;
    __syncthreads();
}

// ---------------------------------------------------------------------------
// Kernel 2: mv1 + fp16 conversion.
// h1 = relu(LN(base)); y = A@h1 in fp32; stream fp16 copy of A to g_Ah.
// ---------------------------------------------------------------------------
__global__ __launch_bounds__(256)
void matvec_conv_kernel(const float* __restrict__ A,
                        float* __restrict__ yout,
                        const float* __restrict__ gamma,
                        const float* __restrict__ beta)
{
    __shared__ float s_h[DH];
    __shared__ float s_red[16];

    const int b = blockIdx.y;
    const int chunk = blockIdx.x;
    const int t = threadIdx.x;
    const int w = t >> 5, lane = t & 31;

    compute_h(g_base + b * DH, nullptr, gamma, beta, s_h, s_red, t);

    const float4* __restrict__ Ab =
        reinterpret_cast<const float4*>(A + (size_t)b * DH * DH);
    const float4* h4 = reinterpret_cast<const float4*>(s_h);

    #pragma unroll
    for (int g = 0; g < 2; g++) {
        const int r0 = chunk * 64 + w * 8 + g * 4;
        const float4* Ar0 = Ab + (size_t)r0 * 256;
        float2* __restrict__ Oh0 =
            reinterpret_cast<float2*>(g_Ah + ((size_t)b * DH + r0) * DH);

        float a0 = 0.f, a1 = 0.f, a2 = 0.f, a3 = 0.f;
        #pragma unroll
        for (int it = 0; it < 8; it++) {
            float4 v0 = __ldcs(Ar0 + lane + it * 32);
            float4 v1 = __ldcs(Ar0 + 256 + lane + it * 32);
            float4 v2 = __ldcs(Ar0 + 512 + lane + it * 32);
            float4 v3 = __ldcs(Ar0 + 768 + lane + it * 32);
            float4 hv = h4[lane + it * 32];
            a0 += v0.x * hv.x + v0.y * hv.y + v0.z * hv.z + v0.w * hv.w;
            a1 += v1.x * hv.x + v1.y * hv.y + v1.z * hv.z + v1.w * hv.w;
            a2 += v2.x * hv.x + v2.y * hv.y + v2.z * hv.z + v2.w * hv.w;
            a3 += v3.x * hv.x + v3.y * hv.y + v3.z * hv.z + v3.w * hv.w;
            __stcs(Oh0 + lane + it * 32,       pack_h4(v0));
            __stcs(Oh0 + 256 + lane + it * 32, pack_h4(v1));
            __stcs(Oh0 + 512 + lane + it * 32, pack_h4(v2));
            __stcs(Oh0 + 768 + lane + it * 32, pack_h4(v3));
        }
        #pragma unroll
        for (int o = 16; o > 0; o >>= 1) {
            a0 += __shfl_xor_sync(0xffffffffu, a0, o);
            a1 += __shfl_xor_sync(0xffffffffu, a1, o);
            a2 += __shfl_xor_sync(0xffffffffu, a2, o);
            a3 += __shfl_xor_sync(0xffffffffu, a3, o);
        }
        if (lane == 0) {
            yout[b * DH + r0]     = a0;
            yout[b * DH + r0 + 1] = a1;
            yout[b * DH + r0 + 2] = a2;
            yout[b * DH + r0 + 3] = a3;
        }
    }
}

// ---------------------------------------------------------------------------
// Kernel 3 (x2): fp16 matvec. h = relu(LN(base + yin)); yout = Ah@h.
// ---------------------------------------------------------------------------
__global__ __launch_bounds__(256)
void matvec_h_kernel(const float* __restrict__ yin,
                     float* __restrict__ yout,
                     const float* __restrict__ gamma,
                     const float* __restrict__ beta)
{
    __shared__ float s_h[DH];
    __shared__ float s_red[16];

    const int b = blockIdx.y;
    const int chunk = blockIdx.x;
    const int t = threadIdx.x;
    const int w = t >> 5, lane = t & 31;

    compute_h(g_base + b * DH, yin + b * DH, gamma, beta, s_h, s_red, t);

    const float4* h4 = reinterpret_cast<const float4*>(s_h);

    #pragma unroll
    for (int g = 0; g < 2; g++) {
        const int r0 = chunk * 64 + w * 8 + g * 4;
        const uint4* __restrict__ R0 =
            reinterpret_cast<const uint4*>(g_Ah + ((size_t)b * DH + r0) * DH);

        float a0 = 0.f, a1 = 0.f, a2 = 0.f, a3 = 0.f;
        #pragma unroll
        for (int it = 0; it < 4; it++) {
            uint4 v0 = __ldcs(R0 + lane + it * 32);
            uint4 v1 = __ldcs(R0 + 128 + lane + it * 32);
            uint4 v2 = __ldcs(R0 + 256 + lane + it * 32);
            uint4 v3 = __ldcs(R0 + 384 + lane + it * 32);
            const int idx = (it * 32 + lane) * 2;
            float4 ha = h4[idx];
            float4 hb = h4[idx + 1];
            a0 += dot8(v0, ha, hb);
            a1 += dot8(v1, ha, hb);
            a2 += dot8(v2, ha, hb);
            a3 += dot8(v3, ha, hb);
        }
        #pragma unroll
        for (int o = 16; o > 0; o >>= 1) {
            a0 += __shfl_xor_sync(0xffffffffu, a0, o);
            a1 += __shfl_xor_sync(0xffffffffu, a1, o);
            a2 += __shfl_xor_sync(0xffffffffu, a2, o);
            a3 += __shfl_xor_sync(0xffffffffu, a3, o);
        }
        if (lane == 0) {
            yout[b * DH + r0]     = a0;
            yout[b * DH + r0 + 1] = a1;
            yout[b * DH + r0 + 2] = a2;
            yout[b * DH + r0 + 3] = a3;
        }
    }
}

// ---------------------------------------------------------------------------
// Kernel 4: h3 = relu(LN(base + yin)) written straight into outH.
// ---------------------------------------------------------------------------
__global__ __launch_bounds__(256)
void h_final_kernel(const float* __restrict__ yin,
                    const float* __restrict__ gamma,
                    const float* __restrict__ beta,
                    float* __restrict__ outH)
{
    __shared__ float s_h[DH];
    __shared__ float s_red[16];
    const int b = blockIdx.x;
    const int t = threadIdx.x;

    compute_h(g_base + b * DH, yin + b * DH, gamma, beta, s_h, s_red, t);
    reinterpret_cast<float4*>(outH + b * DH)[t] =
        reinterpret_cast<const float4*>(s_h)[t];
}

// ---------------------------------------------------------------------------
// Kernel 5: pure-stream Hebbian update reading the FP16 copy of A.
// A_k = LAM*fp16(A) + ETA*h3 h3^T. Traffic: 268MB read + 537MB write.
// grid = (64 chunks of 16 rows, 128 batches), 256 thr, pipelined 4 rows.
// ---------------------------------------------------------------------------
__global__ __launch_bounds__(256)
void update_stream_kernel(const float* __restrict__ h3,   // = outH
                          float* __restrict__ outA)
{
    const int b = blockIdx.y;
    const int chunk = blockIdx.x;
    const int t = threadIdx.x;
    const int row0 = chunk * 16;

    const uint2* __restrict__ Ab =
        reinterpret_cast<const uint2*>(g_Ah + (size_t)b * DH * DH) +
        (size_t)row0 * 256;                       // 256 uint2 per row
    float4* __restrict__ Ob =
        reinterpret_cast<float4*>(outA + (size_t)b * DH * DH) +
        (size_t)row0 * 256;

    const float4 hv = __ldg(reinterpret_cast<const float4*>(h3 + b * DH) + t);

    float hr[16];
    #pragma unroll
    for (int r = 0; r < 16; r++)
        hr[r] = __ldg(h3 + b * DH + row0 + r) * ETA;

    uint2 c0 = __ldcs(Ab + 0 * 256 + t);
    uint2 c1 = __ldcs(Ab + 1 * 256 + t);
    uint2 c2 = __ldcs(Ab + 2 * 256 + t);
    uint2 c3 = __ldcs(Ab + 3 * 256 + t);

    #pragma unroll
    for (int g = 0; g < 4; g++) {
        uint2 n0, n1, n2, n3;
        if (g < 3) {
            const uint2* An = Ab + (size_t)(g + 1) * 4 * 256 + t;
            n0 = __ldcs(An + 0 * 256);
            n1 = __ldcs(An + 1 * 256);
            n2 = __ldcs(An + 2 * 256);
            n3 = __ldcs(An + 3 * 256);
        }
        float4* Og = Ob + (size_t)g * 4 * 256 + t;
        const float h0 = hr[g * 4 + 0];
        const float h1 = hr[g * 4 + 1];
        const float h2 = hr[g * 4 + 2];
        const float h3v = hr[g * 4 + 3];
        float4 a, o;
        a = unpack_h4(c0);
        o.x = fmaf(LAM, a.x, h0 * hv.x); o.y = fmaf(LAM, a.y, h0 * hv.y);
        o.z = fmaf(LAM, a.z, h0 * hv.z); o.w = fmaf(LAM, a.w, h0 * hv.w);
        __stcs(Og + 0 * 256, o);
        a = unpack_h4(c1);
        o.x = fmaf(LAM, a.x, h1 * hv.x); o.y = fmaf(LAM, a.y, h1 * hv.y);
        o.z = fmaf(LAM, a.z, h1 * hv.z); o.w = fmaf(LAM, a.w, h1 * hv.w);
        __stcs(Og + 1 * 256, o);
        a = unpack_h4(c2);
        o.x = fmaf(LAM, a.x, h2 * hv.x); o.y = fmaf(LAM, a.y, h2 * hv.y);
        o.z = fmaf(LAM, a.z, h2 * hv.z); o.w = fmaf(LAM, a.w, h2 * hv.w);
        __stcs(Og + 2 * 256, o);
        a = unpack_h4(c3);
        o.x = fmaf(LAM, a.x, h3v * hv.x); o.y = fmaf(LAM, a.y, h3v * hv.y);
        o.z = fmaf(LAM, a.z, h3v * hv.z); o.w = fmaf(LAM, a.w, h3v * hv.w);
        __stcs(Og + 3 * 256, o);
        c0 = n0; c1 = n1; c2 = n2; c3 = n3;
    }
}

// ---------------------------------------------------------------------------
extern "C" void kernel_launch(void* const* d_in, const int* in_sizes, int n_in,
                              void* d_out, int out_size)
{
    const float* z      = (const float*)d_in[0];
    const float* h_prev = (const float*)d_in[1];
    const float* A_prev = (const float*)d_in[2];
    const float* W_h    = (const float*)d_in[3];
    const float* W_g    = (const float*)d_in[4];
    const float* b_h    = (const float*)d_in[5];
    const float* gamma  = (const float*)d_in[6];
    const float* beta   = (const float*)d_in[7];

    float* outH = (float*)d_out;                 // h_t: 128*1024
    float* outA = (float*)d_out + BATCH * DH;    // A_k: 128*1024*1024

    float* y0;  cudaGetSymbolAddress((void**)&y0, g_y0);
    float* y1;  cudaGetSymbolAddress((void**)&y1, g_y1);

    base_gemm_kernel<<<dim3(BATCH / 32, DH / 32), 256>>>(h_prev, z, W_h, W_g, b_h);

    matvec_conv_kernel<<<dim3(16, BATCH), 256>>>(A_prev, y0, gamma, beta);
    matvec_h_kernel<<<dim3(16, BATCH), 256>>>(y0, y1, gamma, beta);
    matvec_h_kernel<<<dim3(16, BATCH), 256>>>(y1, y0, gamma, beta);

    h_final_kernel<<<BATCH, 256>>>(y0, gamma, beta, outH);
    update_stream_kernel<<<dim3(64, BATCH), 256>>>(outH, outA);
}